// round 5
// baseline (speedup 1.0000x reference)
#include <cuda_runtime.h>
#include <cuda_fp16.h>
#include <cstdint>
#include <math.h>

#define NB 64
#define TT 512
#define EE 512
#define KK 512
#define VV 512
#define BKH 32                // K halves per chunk
#define SMS 40                // smem row stride in halves (32 + 8 pad)

// ---------------------------------------------------------------------------
// Device scratch
// ---------------------------------------------------------------------------
__device__ __half g_xh [(size_t)NB * TT * EE];
__device__ __half g_WTh[(size_t)3 * EE * KK];
__device__ __half g_Qh [(size_t)NB * TT * KK];
__device__ __half g_Kh [(size_t)NB * TT * KK];
__device__ __half g_Vh [(size_t)NB * TT * VV];
__device__ __half g_Vth[(size_t)NB * TT * VV];
__device__ float  g_S  [(size_t)NB * TT * TT];
__device__ __half g_Sh [(size_t)NB * TT * TT];

// ---------------------------------------------------------------------------
// Helpers
// ---------------------------------------------------------------------------
__device__ __forceinline__ uint32_t smem_u32(const void* p) {
    uint32_t a;
    asm("{ .reg .u64 t; cvta.to.shared.u64 t, %1; cvt.u32.u64 %0, t; }"
        : "=r"(a) : "l"(p));
    return a;
}

#define CP_ASYNC16(dst, src) \
    asm volatile("cp.async.cg.shared.global [%0], [%1], 16;" \
                 :: "r"(dst), "l"(src) : "memory")
#define CP_COMMIT() asm volatile("cp.async.commit_group;" ::: "memory")
#define CP_WAIT0()  asm volatile("cp.async.wait_group 0;" ::: "memory")

#define LDSM_X4(r0, r1, r2, r3, addr)                                   \
    asm volatile("ldmatrix.sync.aligned.m8n8.x4.shared.b16 "            \
                 "{%0,%1,%2,%3}, [%4];"                                 \
                 : "=r"(r0), "=r"(r1), "=r"(r2), "=r"(r3) : "r"(addr))

__device__ __forceinline__ void mma_f16(float* c, const uint32_t* a,
                                        const uint32_t* b) {
    asm volatile(
        "mma.sync.aligned.m16n8k16.row.col.f32.f16.f16.f32 "
        "{%0,%1,%2,%3}, {%4,%5,%6,%7}, {%8,%9}, {%0,%1,%2,%3};"
        : "+f"(c[0]), "+f"(c[1]), "+f"(c[2]), "+f"(c[3])
        : "r"(a[0]), "r"(a[1]), "r"(a[2]), "r"(a[3]), "r"(b[0]), "r"(b[1]));
}

// ---------------------------------------------------------------------------
// Dynamic shared tiles: A 256 rows, B 128 rows, stride SMS (conflict-free,
// layout identical to the verified R4 pattern).
// ---------------------------------------------------------------------------
struct __align__(16) SmemT {
    __half A[2][256][SMS];   // 40960 B
    __half B[2][128][SMS];   // 20480 B
};
#define SMEM_BYTES (sizeof(SmemT))   // 61440

template <int ROWS>
__device__ __forceinline__ void load_tile(__half (*dst)[SMS],
                                          const __half* __restrict__ gsrc,
                                          int ldh, int tid) {
    unsigned long long gb = (unsigned long long)__cvta_generic_to_global(gsrc);
    #pragma unroll
    for (int i = 0; i < ROWS / 64; ++i) {
        int ch  = i * 256 + tid;
        int row = ch >> 2;
        int off = ch & 3;
        uint32_t d = smem_u32(&dst[row][off * 8]);
        unsigned long long s = gb + (unsigned long long)row * ((size_t)ldh * 2)
                                  + (unsigned)off * 16;
        CP_ASYNC16(d, s);
    }
}

// One BKH=32 chunk for a 64x64 warp tile: 2 k16-steps x (4 mt x 8 nt) MMAs.
__device__ __forceinline__ void compute_chunk(const __half (*As)[SMS],
                                              const __half (*Bs)[SMS],
                                              float c[4][8][4],
                                              int wr, int wc, int lane) {
    const int arow = lane & 15;
    const int asel = (lane >> 4) * 8;
    const int bn   = (lane & 7) + ((lane >> 4) << 3);
    const int bsel = ((lane >> 3) & 1) * 8;
    #pragma unroll
    for (int ks = 0; ks < 2; ++ks) {
        const int kh = ks * 16;
        uint32_t a[4][4], b[8][2];
        #pragma unroll
        for (int mt = 0; mt < 4; ++mt) {
            uint32_t ad = smem_u32(&As[wr * 64 + mt * 16 + arow][kh + asel]);
            LDSM_X4(a[mt][0], a[mt][1], a[mt][2], a[mt][3], ad);
        }
        #pragma unroll
        for (int np = 0; np < 4; ++np) {
            uint32_t r0, r1, r2, r3;
            uint32_t ad = smem_u32(&Bs[wc * 64 + np * 16 + bn][kh + bsel]);
            LDSM_X4(r0, r1, r2, r3, ad);
            b[np * 2][0] = r0;     b[np * 2][1] = r1;
            b[np * 2 + 1][0] = r2; b[np * 2 + 1][1] = r3;
        }
        #pragma unroll
        for (int mt = 0; mt < 4; ++mt)
            #pragma unroll
            for (int nt = 0; nt < 8; ++nt)
                mma_f16(c[mt][nt], a[mt], b[nt]);
    }
}

// Mainloop: C[256x128] += A[256,K] . B[128,K]^T, nc chunks of BKH.
__device__ __forceinline__ void gemm_mainloop(SmemT& sm,
                                              const __half* __restrict__ A, int lda,
                                              const __half* __restrict__ B, int ldb,
                                              int nc, int tid,
                                              float c[4][8][4],
                                              int wr, int wc, int lane) {
    load_tile<256>(sm.A[0], A, lda, tid);
    load_tile<128>(sm.B[0], B, ldb, tid);
    CP_COMMIT();

    for (int ch = 0; ch < nc; ++ch) {
        const int buf = ch & 1;
        CP_WAIT0();
        __syncthreads();
        if (ch + 1 < nc) {
            load_tile<256>(sm.A[1 - buf], A + (size_t)(ch + 1) * BKH, lda, tid);
            load_tile<128>(sm.B[1 - buf], B + (size_t)(ch + 1) * BKH, ldb, tid);
            CP_COMMIT();
        }
        compute_chunk(sm.A[buf], sm.B[buf], c, wr, wc, lane);
    }
}

__device__ __forceinline__ void zero_acc(float c[4][8][4]) {
    #pragma unroll
    for (int i = 0; i < 4; ++i)
        #pragma unroll
        for (int j = 0; j < 8; ++j)
            #pragma unroll
            for (int k = 0; k < 4; ++k) c[i][j][k] = 0.0f;
}

// ---------------------------------------------------------------------------
// GEMM kernels (256 threads = 8 warps, wr in 0..3, wc in 0..1)
// ---------------------------------------------------------------------------
__global__ __launch_bounds__(256) void proj_mma(const float* __restrict__ bq,
                                                const float* __restrict__ bk,
                                                const float* __restrict__ bv) {
    extern __shared__ char smem_raw[];
    SmemT& sm = *(SmemT*)smem_raw;
    const int tid = threadIdx.x, lane = tid & 31, wid = tid >> 5;
    const int wr = wid >> 1, wc = wid & 1;
    const int colT = blockIdx.x, rowT = blockIdx.y, which = blockIdx.z;

    const __half* A = g_xh + (size_t)rowT * 256 * EE;
    const __half* B = g_WTh + (size_t)which * EE * KK + (size_t)colT * 128 * EE;
    __half* Cmat = (which == 0) ? g_Qh : ((which == 1) ? g_Kh : g_Vh);
    const float* bias = (which == 0) ? bq : ((which == 1) ? bk : bv);

    float c[4][8][4];
    zero_acc(c);
    gemm_mainloop(sm, A, EE, B, EE, EE / BKH, tid, c, wr, wc, lane);

    __half* Crow = Cmat + (size_t)rowT * 256 * KK;
    const int g = lane >> 2, q = lane & 3;
    #pragma unroll
    for (int mt = 0; mt < 4; ++mt) {
        #pragma unroll
        for (int nt = 0; nt < 8; ++nt) {
            const int row = wr * 64 + mt * 16 + g;
            const int col = colT * 128 + wc * 64 + nt * 8 + q * 2;
            float b0 = __ldg(bias + col), b1 = __ldg(bias + col + 1);
            *(__half2*)&Crow[(size_t)row * KK + col] =
                __floats2half2_rn(c[mt][nt][0] + b0, c[mt][nt][1] + b1);
            *(__half2*)&Crow[(size_t)(row + 8) * KK + col] =
                __floats2half2_rn(c[mt][nt][2] + b0, c[mt][nt][3] + b1);
        }
    }
}

// Valid 256x128 score tiles (t-tile of 256 rows, s-tile of 128 cols)
__constant__ int PT2[6] = {0, 0, 1, 1, 1, 1};
__constant__ int PS2[6] = {0, 1, 0, 1, 2, 3};

__global__ __launch_bounds__(256) void qkt_mma() {
    extern __shared__ char smem_raw[];
    SmemT& sm = *(SmemT*)smem_raw;
    const int tid = threadIdx.x, lane = tid & 31, wid = tid >> 5;
    const int wr = wid >> 1, wc = wid & 1;
    const int tT = PT2[blockIdx.x], sT = PS2[blockIdx.x], b = blockIdx.y;

    const __half* A = g_Qh + (size_t)b * TT * KK + (size_t)tT * 256 * KK;
    const __half* B = g_Kh + (size_t)b * TT * KK + (size_t)sT * 128 * KK;

    float c[4][8][4];
    zero_acc(c);
    gemm_mainloop(sm, A, KK, B, KK, KK / BKH, tid, c, wr, wc, lane);

    const float SCALE = 0.04419417382415922f;   // 1/sqrt(512)
    float* Crow = g_S + (size_t)b * TT * TT + (size_t)tT * 256 * TT;
    const int g = lane >> 2, q = lane & 3;
    #pragma unroll
    for (int mt = 0; mt < 4; ++mt) {
        #pragma unroll
        for (int nt = 0; nt < 8; ++nt) {
            const int row = wr * 64 + mt * 16 + g;
            const int col = sT * 128 + wc * 64 + nt * 8 + q * 2;
            *(float2*)&Crow[(size_t)row * TT + col] =
                make_float2(c[mt][nt][0] * SCALE, c[mt][nt][1] * SCALE);
            *(float2*)&Crow[(size_t)(row + 8) * TT + col] =
                make_float2(c[mt][nt][2] * SCALE, c[mt][nt][3] * SCALE);
        }
    }
}

__global__ __launch_bounds__(256) void av_mma(float* __restrict__ out) {
    extern __shared__ char smem_raw[];
    SmemT& sm = *(SmemT*)smem_raw;
    const int tid = threadIdx.x, lane = tid & 31, wid = tid >> 5;
    const int wr = wid >> 1, wc = wid & 1;
    const int vT = blockIdx.x, tT = blockIdx.y, b = blockIdx.z;

    const __half* A = g_Sh  + (size_t)b * TT * TT + (size_t)tT * 256 * TT;
    const __half* B = g_Vth + (size_t)b * TT * VV + (size_t)vT * 128 * TT;
    const int nc = (tT + 1) * (256 / BKH);   // causal K cutoff

    float c[4][8][4];
    zero_acc(c);
    gemm_mainloop(sm, A, TT, B, TT, nc, tid, c, wr, wc, lane);

    float* Crow = out + (size_t)b * TT * VV + (size_t)tT * 256 * VV;
    const int g = lane >> 2, q = lane & 3;
    #pragma unroll
    for (int mt = 0; mt < 4; ++mt) {
        #pragma unroll
        for (int nt = 0; nt < 8; ++nt) {
            const int row = wr * 64 + mt * 16 + g;
            const int col = vT * 128 + wc * 64 + nt * 8 + q * 2;
            *(float2*)&Crow[(size_t)row * VV + col] =
                make_float2(c[mt][nt][0], c[mt][nt][1]);
            *(float2*)&Crow[(size_t)(row + 8) * VV + col] =
                make_float2(c[mt][nt][2], c[mt][nt][3]);
        }
    }
}

// ---------------------------------------------------------------------------
// Aux kernels
// ---------------------------------------------------------------------------
__global__ __launch_bounds__(256) void convx_kernel(const float* __restrict__ x) {
    size_t i = ((size_t)blockIdx.x * 256 + threadIdx.x) * 4;
    float4 v = *(const float4*)(x + i);
    __half2* d = (__half2*)(g_xh + i);
    d[0] = __floats2half2_rn(v.x, v.y);
    d[1] = __floats2half2_rn(v.z, v.w);
}

__global__ __launch_bounds__(256) void wtrans_kernel(const float* __restrict__ Wq,
                                                     const float* __restrict__ Wk,
                                                     const float* __restrict__ Wv) {
    __shared__ float t[32][33];
    const int which = blockIdx.z;
    const float* W = (which == 0) ? Wq : ((which == 1) ? Wk : Wv);
    __half* WT = g_WTh + (size_t)which * EE * KK;
    const int bx = blockIdx.x * 32, by = blockIdx.y * 32;
    #pragma unroll
    for (int j = 0; j < 32; j += 8)
        t[threadIdx.y + j][threadIdx.x] =
            W[(size_t)(by + threadIdx.y + j) * KK + bx + threadIdx.x];
    __syncthreads();
    #pragma unroll
    for (int j = 0; j < 32; j += 8)
        WT[(size_t)(bx + threadIdx.y + j) * EE + by + threadIdx.x] =
            __float2half(t[threadIdx.x][threadIdx.y + j]);
}

__global__ __launch_bounds__(256) void vtrans_kernel() {
    __shared__ __half t[32][34];
    const int b = blockIdx.z;
    const __half* V = g_Vh + (size_t)b * TT * VV;
    __half* Vt = g_Vth + (size_t)b * TT * VV;
    const int bx = blockIdx.x * 32, by = blockIdx.y * 32;
    #pragma unroll
    for (int j = 0; j < 32; j += 8)
        t[threadIdx.y + j][threadIdx.x] =
            V[(size_t)(by + threadIdx.y + j) * VV + bx + threadIdx.x];
    __syncthreads();
    #pragma unroll
    for (int j = 0; j < 32; j += 8)
        Vt[(size_t)(bx + threadIdx.y + j) * TT + by + threadIdx.x] =
            t[threadIdx.x][threadIdx.y + j];
}

// Column softmax (axis = t). One thread per column s. Writes FULL zero-filled
// columns so av_mma's 256-row tiles never read unwritten attn entries.
__global__ __launch_bounds__(128) void softmax_kernel() {
    const int b = blockIdx.y;
    const int s = blockIdx.x * 128 + threadIdx.x;
    const float* Sb = g_S + (size_t)b * TT * TT;
    __half* Sh = g_Sh + (size_t)b * TT * TT;
    const int w0 = blockIdx.x * 128 + (threadIdx.x & ~31);

    float m = -1e30f;
    #pragma unroll 4
    for (int t = w0; t < TT; ++t) {
        float xv = Sb[(size_t)t * TT + s];
        if (t >= s) m = fmaxf(m, xv);
    }
    float sum = 0.0f;
    #pragma unroll 4
    for (int t = w0; t < TT; ++t) {
        float xv = Sb[(size_t)t * TT + s];
        if (t >= s) sum += __expf(xv - m);
    }
    const float inv = 1.0f / sum;
    #pragma unroll 4
    for (int t = 0; t < TT; ++t) {
        float r = 0.0f;
        if (t >= s) r = __expf(Sb[(size_t)t * TT + s] - m) * inv;
        Sh[(size_t)t * TT + s] = __float2half(r);
    }
}

// ---------------------------------------------------------------------------
extern "C" void kernel_launch(void* const* d_in, const int* in_sizes, int n_in,
                              void* d_out, int out_size) {
    const float* x  = (const float*)d_in[0];
    const float* Wq = (const float*)d_in[1];
    const float* bq = (const float*)d_in[2];
    const float* Wk = (const float*)d_in[3];
    const float* bk = (const float*)d_in[4];
    const float* Wv = (const float*)d_in[5];
    const float* bv = (const float*)d_in[6];
    float* out = (float*)d_out;

    cudaFuncSetAttribute(proj_mma, cudaFuncAttributeMaxDynamicSharedMemorySize, SMEM_BYTES);
    cudaFuncSetAttribute(qkt_mma,  cudaFuncAttributeMaxDynamicSharedMemorySize, SMEM_BYTES);
    cudaFuncSetAttribute(av_mma,   cudaFuncAttributeMaxDynamicSharedMemorySize, SMEM_BYTES);

    convx_kernel <<<(NB * TT * EE) / (256 * 4), 256>>>(x);
    wtrans_kernel<<<dim3(16, 16, 3), dim3(32, 8)>>>(Wq, Wk, Wv);
    proj_mma     <<<dim3(4, 128, 3), 256, SMEM_BYTES>>>(bq, bk, bv);
    vtrans_kernel<<<dim3(16, 16, 64), dim3(32, 8)>>>();
    qkt_mma      <<<dim3(6, 64), 256, SMEM_BYTES>>>();
    softmax_kernel<<<dim3(4, 64), 128>>>();
    av_mma       <<<dim3(4, 2, 64), 256, SMEM_BYTES>>>(out);
}

// round 6
// speedup vs baseline: 1.1773x; 1.1773x over previous
#include <cuda_runtime.h>
#include <cuda_fp16.h>
#include <cstdint>
#include <math.h>

#define NB 64
#define TT 512
#define EE 512
#define KK 512
#define VV 512
#define BKH 64                  // K halves per chunk
#define SA  72                  // A/B-nt smem row stride (64 + 8 pad)
#define SBT 136                 // B-trans smem row stride (128 + 8 pad)

#define ABYTES  (128 * SA * 2)              // 18432
#define STAGE   (ABYTES + 128 * SA * 2)     // 36864 (B slot sized for max)
#define SMEM_BYTES (2 * STAGE)              // 73728

// ---------------------------------------------------------------------------
// Device scratch
// ---------------------------------------------------------------------------
__device__ __half g_xh[(size_t)NB * TT * EE];
__device__ __half g_Wh[(size_t)3 * EE * KK];    // W in natural [e][k] fp16
__device__ __half g_Qh[(size_t)NB * TT * KK];
__device__ __half g_Kh[(size_t)NB * TT * KK];
__device__ __half g_Vh[(size_t)NB * TT * VV];   // V natural [t][v] fp16
__device__ float  g_S [(size_t)NB * TT * TT];
__device__ __half g_Sh[(size_t)NB * TT * TT];

// ---------------------------------------------------------------------------
// Helpers
// ---------------------------------------------------------------------------
__device__ __forceinline__ uint32_t smem_u32(const void* p) {
    uint32_t a;
    asm("{ .reg .u64 t; cvta.to.shared.u64 t, %1; cvt.u32.u64 %0, t; }"
        : "=r"(a) : "l"(p));
    return a;
}

#define CP_ASYNC16(dst, src) \
    asm volatile("cp.async.cg.shared.global [%0], [%1], 16;" \
                 :: "r"(dst), "l"(src) : "memory")
#define CP_COMMIT() asm volatile("cp.async.commit_group;" ::: "memory")
#define CP_WAIT0()  asm volatile("cp.async.wait_group 0;" ::: "memory")

#define LDSM_X4(r0, r1, r2, r3, addr)                                   \
    asm volatile("ldmatrix.sync.aligned.m8n8.x4.shared.b16 "            \
                 "{%0,%1,%2,%3}, [%4];"                                 \
                 : "=r"(r0), "=r"(r1), "=r"(r2), "=r"(r3) : "r"(addr))

#define LDSM_X4_T(r0, r1, r2, r3, addr)                                 \
    asm volatile("ldmatrix.sync.aligned.m8n8.x4.trans.shared.b16 "      \
                 "{%0,%1,%2,%3}, [%4];"                                 \
                 : "=r"(r0), "=r"(r1), "=r"(r2), "=r"(r3) : "r"(addr))

__device__ __forceinline__ void mma_f16(float* c, const uint32_t* a,
                                        const uint32_t* b) {
    asm volatile(
        "mma.sync.aligned.m16n8k16.row.col.f32.f16.f16.f32 "
        "{%0,%1,%2,%3}, {%4,%5,%6,%7}, {%8,%9}, {%0,%1,%2,%3};"
        : "+f"(c[0]), "+f"(c[1]), "+f"(c[2]), "+f"(c[3])
        : "r"(a[0]), "r"(a[1]), "r"(a[2]), "r"(a[3]), "r"(b[0]), "r"(b[1]));
}

// ---------------------------------------------------------------------------
// Tile loaders (cp.async, 16B, conflict-free phases)
// ---------------------------------------------------------------------------
// 128 rows x 64 halves, row stride SA (A operand and NT B operand)
__device__ __forceinline__ void load_tile_k(__half* dst,
                                            const __half* __restrict__ gsrc,
                                            int ldh, int tid) {
    unsigned long long gb = (unsigned long long)__cvta_generic_to_global(gsrc);
    #pragma unroll
    for (int i = 0; i < 4; ++i) {
        int ch  = i * 256 + tid;           // 0..1023
        int row = ch >> 3;
        int off = ch & 7;
        uint32_t d = smem_u32(dst + row * SA + off * 8);
        unsigned long long s = gb + (unsigned long long)row * ((size_t)ldh * 2)
                                  + (unsigned)off * 16;
        CP_ASYNC16(d, s);
    }
}

// 64 rows x 128 halves, row stride SBT (trans B operand: rows = k)
__device__ __forceinline__ void load_tile_t(__half* dst,
                                            const __half* __restrict__ gsrc,
                                            int ldh, int tid) {
    unsigned long long gb = (unsigned long long)__cvta_generic_to_global(gsrc);
    #pragma unroll
    for (int i = 0; i < 4; ++i) {
        int ch  = i * 256 + tid;           // 0..1023
        int row = ch >> 4;
        int off = ch & 15;
        uint32_t d = smem_u32(dst + row * SBT + off * 8);
        unsigned long long s = gb + (unsigned long long)row * ((size_t)ldh * 2)
                                  + (unsigned)off * 16;
        CP_ASYNC16(d, s);
    }
}

// ---------------------------------------------------------------------------
// One BKH=64 chunk for a 64x32 warp tile: 4 k16-steps x (4 mt x 4 nt) MMAs.
// TRB=false: B in smem as [n][k] (stride SA), non-trans ldmatrix.
// TRB=true:  B in smem as [k][n] (stride SBT), trans ldmatrix.
// ---------------------------------------------------------------------------
template <bool TRB>
__device__ __forceinline__ void compute_chunk(const __half* As, const __half* Bs,
                                              float c[4][4][4],
                                              int wr, int wc, int lane) {
    const int arow  = lane & 15;
    const int asel  = (lane >> 4) * 8;
    const int bn    = (lane & 7) + ((lane >> 4) << 3);   // NT path
    const int bsel  = ((lane >> 3) & 1) * 8;
    const int tkrow = (lane & 7) + ((lane >> 3) & 1) * 8; // TR path
    const int tnoff = (lane >> 4) * 8;
    #pragma unroll
    for (int ks = 0; ks < 4; ++ks) {
        const int kh = ks * 16;
        uint32_t a[4][4], b[4][2];
        #pragma unroll
        for (int mt = 0; mt < 4; ++mt) {
            uint32_t ad = smem_u32(As + (wr * 64 + mt * 16 + arow) * SA + kh + asel);
            LDSM_X4(a[mt][0], a[mt][1], a[mt][2], a[mt][3], ad);
        }
        #pragma unroll
        for (int np = 0; np < 2; ++np) {
            uint32_t r0, r1, r2, r3;
            if (!TRB) {
                uint32_t ad = smem_u32(Bs + (wc * 32 + np * 16 + bn) * SA + kh + bsel);
                LDSM_X4(r0, r1, r2, r3, ad);
            } else {
                uint32_t ad = smem_u32(Bs + (kh + tkrow) * SBT
                                          + wc * 32 + np * 16 + tnoff);
                LDSM_X4_T(r0, r1, r2, r3, ad);
            }
            b[np * 2][0] = r0;     b[np * 2][1] = r1;
            b[np * 2 + 1][0] = r2; b[np * 2 + 1][1] = r3;
        }
        #pragma unroll
        for (int mt = 0; mt < 4; ++mt)
            #pragma unroll
            for (int nt = 0; nt < 4; ++nt)
                mma_f16(c[mt][nt], a[mt], b[nt]);
    }
}

// Mainloop: C[128x128] += A[128,K] . op(B), nc chunks of BKH, double-buffered.
template <bool TRB>
__device__ __forceinline__ void gemm_mainloop(char* smem,
                                              const __half* __restrict__ A, int lda,
                                              const __half* __restrict__ B, int ldb,
                                              int nc, int tid,
                                              float c[4][4][4],
                                              int wr, int wc, int lane) {
    __half* As0 = (__half*)(smem);
    __half* Bs0 = (__half*)(smem + ABYTES);
    __half* As1 = (__half*)(smem + STAGE);
    __half* Bs1 = (__half*)(smem + STAGE + ABYTES);

    load_tile_k(As0, A, lda, tid);
    if (TRB) load_tile_t(Bs0, B, ldb, tid);
    else     load_tile_k(Bs0, B, ldb, tid);
    CP_COMMIT();

    for (int ch = 0; ch < nc; ++ch) {
        const int buf = ch & 1;
        CP_WAIT0();
        __syncthreads();
        if (ch + 1 < nc) {
            __half* An = buf ? As0 : As1;
            __half* Bn = buf ? Bs0 : Bs1;
            load_tile_k(An, A + (size_t)(ch + 1) * BKH, lda, tid);
            if (TRB) load_tile_t(Bn, B + (size_t)(ch + 1) * BKH * ldb, ldb, tid);
            else     load_tile_k(Bn, B + (size_t)(ch + 1) * BKH, ldb, tid);
            CP_COMMIT();
        }
        compute_chunk<TRB>(buf ? As1 : As0, buf ? Bs1 : Bs0, c, wr, wc, lane);
    }
}

__device__ __forceinline__ void zero_acc(float c[4][4][4]) {
    #pragma unroll
    for (int i = 0; i < 4; ++i)
        #pragma unroll
        for (int j = 0; j < 4; ++j)
            #pragma unroll
            for (int k = 0; k < 4; ++k) c[i][j][k] = 0.0f;
}

// ---------------------------------------------------------------------------
// GEMM kernels: 256 threads = 8 warps (wr 0..1, wc 0..3), CTA tile 128x128
// ---------------------------------------------------------------------------
// Projections: out = x @ W + b (W natural layout, TRB path)
__global__ __launch_bounds__(256) void proj_mma(const float* __restrict__ bq,
                                                const float* __restrict__ bk,
                                                const float* __restrict__ bv) {
    extern __shared__ char smem_raw[];
    const int tid = threadIdx.x, lane = tid & 31, wid = tid >> 5;
    const int wr = wid >> 2, wc = wid & 3;
    const int colT = blockIdx.x, rowT = blockIdx.y, which = blockIdx.z;

    const __half* A = g_xh + (size_t)rowT * 128 * EE;
    const __half* B = g_Wh + (size_t)which * EE * KK + colT * 128;
    __half* Cmat = (which == 0) ? g_Qh : ((which == 1) ? g_Kh : g_Vh);
    const float* bias = (which == 0) ? bq : ((which == 1) ? bk : bv);

    float c[4][4][4];
    zero_acc(c);
    gemm_mainloop<true>(smem_raw, A, EE, B, KK, EE / BKH, tid, c, wr, wc, lane);

    __half* Crow = Cmat + (size_t)rowT * 128 * KK;
    const int g = lane >> 2, q = lane & 3;
    #pragma unroll
    for (int mt = 0; mt < 4; ++mt) {
        #pragma unroll
        for (int nt = 0; nt < 4; ++nt) {
            const int row = wr * 64 + mt * 16 + g;
            const int col = colT * 128 + wc * 32 + nt * 8 + q * 2;
            float b0 = __ldg(bias + col), b1 = __ldg(bias + col + 1);
            *(__half2*)&Crow[(size_t)row * KK + col] =
                __floats2half2_rn(c[mt][nt][0] + b0, c[mt][nt][1] + b1);
            *(__half2*)&Crow[(size_t)(row + 8) * KK + col] =
                __floats2half2_rn(c[mt][nt][2] + b0, c[mt][nt][3] + b1);
        }
    }
}

__constant__ int PT[10] = {0, 1, 1, 2, 2, 2, 3, 3, 3, 3};
__constant__ int PS[10] = {0, 0, 1, 0, 1, 2, 0, 1, 2, 3};

// Scores: S = scale * Q K^T (NT path), lower-triangular tiles only
__global__ __launch_bounds__(256) void qkt_mma() {
    extern __shared__ char smem_raw[];
    const int tid = threadIdx.x, lane = tid & 31, wid = tid >> 5;
    const int wr = wid >> 2, wc = wid & 3;
    const int tT = PT[blockIdx.x], sT = PS[blockIdx.x], b = blockIdx.y;

    const __half* A = g_Qh + (size_t)b * TT * KK + (size_t)tT * 128 * KK;
    const __half* B = g_Kh + (size_t)b * TT * KK + (size_t)sT * 128 * KK;

    float c[4][4][4];
    zero_acc(c);
    gemm_mainloop<false>(smem_raw, A, KK, B, KK, KK / BKH, tid, c, wr, wc, lane);

    const float SCALE = 0.04419417382415922f;   // 1/sqrt(512)
    float* Crow = g_S + (size_t)b * TT * TT + (size_t)tT * 128 * TT;
    const int g = lane >> 2, q = lane & 3;
    #pragma unroll
    for (int mt = 0; mt < 4; ++mt) {
        #pragma unroll
        for (int nt = 0; nt < 4; ++nt) {
            const int row = wr * 64 + mt * 16 + g;
            const int col = sT * 128 + wc * 32 + nt * 8 + q * 2;
            *(float2*)&Crow[(size_t)row * TT + col] =
                make_float2(c[mt][nt][0] * SCALE, c[mt][nt][1] * SCALE);
            *(float2*)&Crow[(size_t)(row + 8) * TT + col] =
                make_float2(c[mt][nt][2] * SCALE, c[mt][nt][3] * SCALE);
        }
    }
}

// Output: out = attn @ V (V natural layout, TRB path), causal K cutoff
__global__ __launch_bounds__(256) void av_mma(float* __restrict__ out) {
    extern __shared__ char smem_raw[];
    const int tid = threadIdx.x, lane = tid & 31, wid = tid >> 5;
    const int wr = wid >> 2, wc = wid & 3;
    const int vT = blockIdx.x, tT = blockIdx.y, b = blockIdx.z;

    const __half* A = g_Sh + (size_t)b * TT * TT + (size_t)tT * 128 * TT;
    const __half* B = g_Vh + (size_t)b * TT * VV + vT * 128;
    const int nc = (tT + 1) * (128 / BKH);

    float c[4][4][4];
    zero_acc(c);
    gemm_mainloop<true>(smem_raw, A, TT, B, VV, nc, tid, c, wr, wc, lane);

    float* Crow = out + (size_t)b * TT * VV + (size_t)tT * 128 * VV;
    const int g = lane >> 2, q = lane & 3;
    #pragma unroll
    for (int mt = 0; mt < 4; ++mt) {
        #pragma unroll
        for (int nt = 0; nt < 4; ++nt) {
            const int row = wr * 64 + mt * 16 + g;
            const int col = vT * 128 + wc * 32 + nt * 8 + q * 2;
            *(float2*)&Crow[(size_t)row * VV + col] =
                make_float2(c[mt][nt][0], c[mt][nt][1]);
            *(float2*)&Crow[(size_t)(row + 8) * VV + col] =
                make_float2(c[mt][nt][2], c[mt][nt][3]);
        }
    }
}

// ---------------------------------------------------------------------------
// Aux kernels
// ---------------------------------------------------------------------------
__global__ __launch_bounds__(256) void convx_kernel(const float* __restrict__ x) {
    size_t i = ((size_t)blockIdx.x * 256 + threadIdx.x) * 4;
    float4 v = *(const float4*)(x + i);
    __half2* d = (__half2*)(g_xh + i);
    d[0] = __floats2half2_rn(v.x, v.y);
    d[1] = __floats2half2_rn(v.z, v.w);
}

__global__ __launch_bounds__(256) void convw_kernel(const float* __restrict__ Wq,
                                                    const float* __restrict__ Wk,
                                                    const float* __restrict__ Wv) {
    const int which = blockIdx.y;
    const float* W = (which == 0) ? Wq : ((which == 1) ? Wk : Wv);
    __half* D = g_Wh + (size_t)which * EE * KK;
    size_t i = ((size_t)blockIdx.x * 256 + threadIdx.x) * 4;
    float4 v = *(const float4*)(W + i);
    __half2* d = (__half2*)(D + i);
    d[0] = __floats2half2_rn(v.x, v.y);
    d[1] = __floats2half2_rn(v.z, v.w);
}

// Column softmax (axis = t), online max/sum in one pass. One thread per s.
__global__ __launch_bounds__(128) void softmax_kernel() {
    const int b = blockIdx.y;
    const int s = blockIdx.x * 128 + threadIdx.x;
    const float* Sb = g_S + (size_t)b * TT * TT;
    __half* Sh = g_Sh + (size_t)b * TT * TT;
    const int tile0 = blockIdx.x * 128;
    const int w0 = tile0 + (threadIdx.x & ~31);

    float m = -1e30f, sum = 0.0f;
    #pragma unroll 2
    for (int t = w0; t < TT; ++t) {
        float xv = Sb[(size_t)t * TT + s];
        if (t >= s) {
            float nm = fmaxf(m, xv);
            sum = sum * __expf(m - nm) + __expf(xv - nm);
            m = nm;
        }
    }
    const float inv = 1.0f / sum;
    #pragma unroll 4
    for (int t = tile0; t < TT; ++t) {
        float r = 0.0f;
        if (t >= s) r = __expf(Sb[(size_t)t * TT + s] - m) * inv;
        Sh[(size_t)t * TT + s] = __float2half(r);
    }
}

// ---------------------------------------------------------------------------
extern "C" void kernel_launch(void* const* d_in, const int* in_sizes, int n_in,
                              void* d_out, int out_size) {
    const float* x  = (const float*)d_in[0];
    const float* Wq = (const float*)d_in[1];
    const float* bq = (const float*)d_in[2];
    const float* Wk = (const float*)d_in[3];
    const float* bk = (const float*)d_in[4];
    const float* Wv = (const float*)d_in[5];
    const float* bv = (const float*)d_in[6];
    float* out = (float*)d_out;

    cudaFuncSetAttribute(proj_mma, cudaFuncAttributeMaxDynamicSharedMemorySize, SMEM_BYTES);
    cudaFuncSetAttribute(qkt_mma,  cudaFuncAttributeMaxDynamicSharedMemorySize, SMEM_BYTES);
    cudaFuncSetAttribute(av_mma,   cudaFuncAttributeMaxDynamicSharedMemorySize, SMEM_BYTES);

    convx_kernel<<<(NB * TT * EE) / (256 * 4), 256>>>(x);
    convw_kernel<<<dim3((EE * KK) / (256 * 4), 3), 256>>>(Wq, Wk, Wv);
    proj_mma    <<<dim3(4, 256, 3), 256, SMEM_BYTES>>>(bq, bk, bv);
    qkt_mma     <<<dim3(10, 64), 256, SMEM_BYTES>>>();
    softmax_kernel<<<dim3(4, 64), 128>>>();
    av_mma      <<<dim3(4, 4, 64), 256, SMEM_BYTES>>>(out);
}